// round 5
// baseline (speedup 1.0000x reference)
#include <cuda_runtime.h>
#include <cuda_bf16.h>
#include <math.h>
#include <stdint.h>

// ---------------- problem constants ----------------
#define HDIM  1024
#define BSZ   4096
#define TLEN  128
#define K2    2048            // stored K: [h_hi | h_lo] / [W_hi | W_lo]
#define NGATE 4096            // 4 gates x HDIM, interleaved n' = j*4 + g
#define MT    256
#define NT    256
#define NCHUNK 32             // K chunks of 32 elems (64B rows, SW64)
#define NSTAGE 3
#define JT    16
#define NCTA  128             // persistent grid
#define NTHREADS 288          // 9 warps: 0=MMA, 1-4=producers, 5-8=epilogue

#if defined(__CUDA_ARCH__) && (defined(__CUDA_ARCH_FEAT_SM103_ALL) || defined(__CUDA_ARCH_FEAT_SM100_ALL) || defined(__CUDA_ARCH_FEAT_SM101_ALL))
#define HAS_TCGEN05 1
#else
#define HAS_TCGEN05 0
#endif

// ---------------- persistent device state ----------------
__device__ __nv_bfloat16 g_A[2][(size_t)BSZ * K2];
__device__ __nv_bfloat16 g_Bp[(size_t)NGATE * K2];
__device__ float g_c[(size_t)BSZ * HDIM];
__device__ float g_biasp[NGATE];
__device__ float g_wihp[NGATE];
__device__ float g_woutp[HDIM];
__device__ float g_partial[2][(size_t)BSZ * JT];
__device__ unsigned g_bar;

// ---------------- smem layout ----------------
#define SM_TMEM   0
#define SM_FULL0  64
#define SM_EMPTY0 (SM_FULL0 + 8*NSTAGE)
#define SM_DONE   (SM_EMPTY0 + 8*NSTAGE)
#define SM_STAGE  1024
#define STAGE_BYTES 65536       // A_hi 16K | A_lo 16K | B_hi 16K | B_lo 16K
#define OFF_AHI 0
#define OFF_ALO 16384
#define OFF_BHI 32768
#define OFF_BLO 49152
#define DSMEM (SM_STAGE + NSTAGE*STAGE_BYTES)
#define N_PROD_THREADS 128

// idesc: F32 accum, BF16 a/b, N=256, M=128
#define MMA_IDESC 0x08400490u

// ---------------- arch-neutral helpers ----------------
__device__ __forceinline__ uint32_t smem_u32(const void* p) {
    uint32_t a;
    asm("{ .reg .u64 t; cvta.to.shared.u64 t, %1; cvt.u32.u64 %0, t; }" : "=r"(a) : "l"(p));
    return a;
}
__device__ __forceinline__ uint32_t elect1() {
    uint32_t r;
    asm volatile("{ .reg .pred p; elect.sync _|p, 0xFFFFFFFF; selp.b32 %0, 1, 0, p; }" : "=r"(r));
    return r;
}
#define MBARRIER_INIT(addr, cnt) \
    asm volatile("mbarrier.init.shared.b64 [%0], %1;" :: "r"((uint32_t)(addr)), "r"((uint32_t)(cnt)) : "memory")
#define MBARRIER_WAIT_PARITY(addr, par) do { \
    uint32_t _m = (uint32_t)(addr); uint32_t _p = (uint32_t)(par); uint32_t _d; \
    asm volatile("{ .reg .pred p; mbarrier.try_wait.parity.acquire.cta.shared::cta.b64 p, [%1], %2; selp.b32 %0,1,0,p; }" \
        : "=r"(_d) : "r"(_m), "r"(_p) : "memory"); \
    if (!_d) { \
        asm volatile("{ .reg .pred P1; WL_%=: mbarrier.try_wait.parity.acquire.cta.shared::cta.b64 P1, [%0], %1, 0x989680; @P1 bra.uni WD_%=; bra.uni WL_%=; WD_%=: }" \
            :: "r"(_m), "r"(_p) : "memory"); \
    } } while (0)
__device__ __forceinline__ void cp16(uint32_t saddr, const void* gaddr) {
    asm volatile("cp.async.cg.shared.global [%0], [%1], 16;" :: "r"(saddr), "l"(gaddr));
}
__device__ __forceinline__ void cp_arrive(uint32_t mbar) {
    asm volatile("cp.async.mbarrier.arrive.noinc.shared::cta.b64 [%0];" :: "r"(mbar) : "memory");
}
__device__ __forceinline__ uint32_t swz64(uint32_t o) { return o ^ ((o >> 3) & 0x30); }

// SW64 K-major smem descriptor: layout 4, version 1, SBO=32, LBO=1
static __device__ __forceinline__ uint64_t make_desc_sw64(uint32_t addr) {
    const uint64_t base = (uint64_t(4) << 61) | (uint64_t(1) << 46) | (uint64_t(32) << 32) | (uint64_t(1) << 16);
    return base | ((uint64_t)(addr >> 4) & 0x3FFF);
}

// software grid barrier (all NCTA CTAs co-resident; reset by prep_state each launch)
#define GRID_SYNC(step) do { \
    __syncthreads(); \
    if (tid == 0) { \
        __threadfence(); \
        atomicAdd(&g_bar, 1u); \
        const unsigned _tgt = (unsigned)NCTA * ((unsigned)(step) + 1u); \
        unsigned _c; \
        do { \
            asm volatile("ld.acquire.gpu.global.u32 %0, [%1];" : "=r"(_c) : "l"(&g_bar) : "memory"); \
            if (_c < _tgt) asm volatile("nanosleep.u32 128;"); \
        } while (_c < _tgt); \
        __threadfence(); \
    } \
    __syncthreads(); \
} while (0)

// ---------------- tcgen05 (sm_103a-only PTX pass) ----------------
#if HAS_TCGEN05
#define TCGEN05_ALLOC(sa, n) \
    asm volatile("tcgen05.alloc.cta_group::1.sync.aligned.shared::cta.b32 [%0], %1;" :: "r"((uint32_t)(sa)), "r"((uint32_t)(n)) : "memory")
#define TCGEN05_DEALLOC(t, n) \
    asm volatile("tcgen05.dealloc.cta_group::1.sync.aligned.b32 %0, %1;" :: "r"(t), "r"((uint32_t)(n)))
#define TCGEN05_RELINQUISH() \
    asm volatile("tcgen05.relinquish_alloc_permit.cta_group::1.sync.aligned;")
#define TCGEN05_COMMIT(mb) \
    asm volatile("tcgen05.commit.cta_group::1.mbarrier::arrive::one.shared::cluster.b64 [%0];" :: "r"((uint32_t)(mb)) : "memory")
#define TCGEN05_FENCE_AFTER()  asm volatile("tcgen05.fence::after_thread_sync;" ::: "memory")
#define TCGEN05_WAIT_LD()      asm volatile("tcgen05.wait::ld.sync.aligned;" ::: "memory")
#define FENCE_PROXY_ASYNC()    asm volatile("fence.proxy.async.shared::cta;" ::: "memory")

#define TCGEN05_LD_X32(r, ta) \
    asm volatile("tcgen05.ld.sync.aligned.32x32b.x32.b32 " \
        "{%0,%1,%2,%3,%4,%5,%6,%7,%8,%9,%10,%11,%12,%13,%14,%15," \
        "%16,%17,%18,%19,%20,%21,%22,%23,%24,%25,%26,%27,%28,%29,%30,%31}, [%32];" \
        : "=r"((r)[0]),"=r"((r)[1]),"=r"((r)[2]),"=r"((r)[3]),"=r"((r)[4]),"=r"((r)[5]),"=r"((r)[6]),"=r"((r)[7]), \
          "=r"((r)[8]),"=r"((r)[9]),"=r"((r)[10]),"=r"((r)[11]),"=r"((r)[12]),"=r"((r)[13]),"=r"((r)[14]),"=r"((r)[15]), \
          "=r"((r)[16]),"=r"((r)[17]),"=r"((r)[18]),"=r"((r)[19]),"=r"((r)[20]),"=r"((r)[21]),"=r"((r)[22]),"=r"((r)[23]), \
          "=r"((r)[24]),"=r"((r)[25]),"=r"((r)[26]),"=r"((r)[27]),"=r"((r)[28]),"=r"((r)[29]),"=r"((r)[30]),"=r"((r)[31]) \
        : "r"(ta))

__device__ __forceinline__ void mma_f16_ss(uint32_t d, uint64_t ad, uint64_t bd, uint32_t en) {
    asm volatile(
        "{ .reg .pred p; setp.ne.u32 p, %4, 0;\n\t"
        "tcgen05.mma.cta_group::1.kind::f16 [%0], %1, %2, %3, {%5,%5,%5,%5}, p; }"
        :: "r"(d), "l"(ad), "l"(bd), "r"(MMA_IDESC), "r"(en), "r"(0u) : "memory");
}
#endif

// ---------------- prep kernels ----------------
__global__ void prep_weights(const float* __restrict__ W_ih, const float* __restrict__ W_hh,
                             const float* __restrict__ b_ih, const float* __restrict__ b_hh,
                             const float* __restrict__ W_out,
                             __nv_bfloat16* __restrict__ Bp, float* __restrict__ biasp,
                             float* __restrict__ wihp, float* __restrict__ woutp)
{
    int idx = blockIdx.x * blockDim.x + threadIdx.x;
    if (idx >= NGATE * HDIM) return;
    int np = idx / HDIM, k = idx - np * HDIM;
    int gg = np & 3, j = np >> 2;
    int src = gg * HDIM + j;
    float w = W_hh[(size_t)src * HDIM + k];
    __nv_bfloat16 hi = __float2bfloat16_rn(w);
    __nv_bfloat16 lo = __float2bfloat16_rn(w - __bfloat162float(hi));
    Bp[(size_t)np * K2 + k]        = hi;
    Bp[(size_t)np * K2 + 1024 + k] = lo;
    if (k == 0) { biasp[np] = b_ih[src] + b_hh[src]; wihp[np] = W_ih[src]; }
    if (np == 0) woutp[k] = W_out[k];
}

__global__ void prep_state(const float* __restrict__ hidden, const float* __restrict__ cell,
                           __nv_bfloat16* __restrict__ A0, float* __restrict__ cbuf)
{
    int idx = blockIdx.x * blockDim.x + threadIdx.x;
    if (idx == 0) g_bar = 0;                 // reset grid barrier each launch
    if (idx >= BSZ * HDIM) return;
    int m = idx / HDIM, k = idx - m * HDIM;
    float h = hidden[idx];
    __nv_bfloat16 hi = __float2bfloat16_rn(h);
    __nv_bfloat16 lo = __float2bfloat16_rn(h - __bfloat162float(hi));
    A0[(size_t)m * K2 + k]        = hi;
    A0[(size_t)m * K2 + 1024 + k] = lo;
    cbuf[idx] = cell[idx];
}

// ---------------- persistent fused LSTM (all 128 steps) ----------------
// gates = W_hi·h_hi + W_hi·h_lo + W_lo·h_hi  (fp32 TMEM accum)
// CTA = (m-tile mx, n-column ny); per step: n-tiles ny and ny+8.
// warp 0: MMA. warps 1-4: cp.async producers. warps 5-8: TMEM epilogue.
__global__ void __launch_bounds__(NTHREADS, 1)
lstm_persist(__nv_bfloat16* __restrict__ Abuf, const __nv_bfloat16* __restrict__ Bp,
             float* __restrict__ cbuf, const float* __restrict__ biasp,
             const float* __restrict__ wihp, const float* __restrict__ woutp,
             float* __restrict__ part, const float* __restrict__ bout,
             float* __restrict__ out)
{
#if HAS_TCGEN05
    extern __shared__ char smem[];
    const uint32_t sbase = smem_u32(smem);
    const int tid = threadIdx.x, wid = tid >> 5, lid = tid & 31;
    const int mx = blockIdx.x & 15, ny = blockIdx.x >> 4;
    const int m0 = mx * MT;
    const size_t NAELEM = (size_t)BSZ * K2;
    const size_t NP = (size_t)BSZ * JT;

    if (tid == 0) {
#pragma unroll
        for (int s = 0; s < NSTAGE; s++) {
            MBARRIER_INIT(sbase + SM_FULL0 + 8 * s, N_PROD_THREADS);
            MBARRIER_INIT(sbase + SM_EMPTY0 + 8 * s, 1);
        }
        MBARRIER_INIT(sbase + SM_DONE, 1);
    }
    if (wid == 0) TCGEN05_ALLOC(sbase + SM_TMEM, 512);
    __syncthreads();
    uint32_t tmem;
    asm volatile("ld.shared.b32 %0, [%1];" : "=r"(tmem) : "r"(sbase + SM_TMEM));

    // pre-arm the epilogue-drain gate so the MMA warp's first bar.sync passes
    if (wid >= 5) asm volatile("bar.arrive 1, 160;");

    if (wid == 0) {
        // ================= MMA warp =================
        TCGEN05_RELINQUISH();
        uint64_t dAhi[NSTAGE], dAlo[NSTAGE], dBhi[NSTAGE], dBlo[NSTAGE];
#pragma unroll
        for (int s = 0; s < NSTAGE; s++) {
            const uint32_t aT = sbase + SM_STAGE + s * STAGE_BYTES;
            dAhi[s] = make_desc_sw64(aT + OFF_AHI);
            dAlo[s] = make_desc_sw64(aT + OFF_ALO);
            dBhi[s] = make_desc_sw64(aT + OFF_BHI);
            dBlo[s] = make_desc_sw64(aT + OFF_BLO);
        }
        int cc = 0;
        for (int t = 0; t < TLEN; t++) {
            for (int tile = 0; tile < 2; tile++) {
                // wait until epilogue finished reading TMEM of previous tile
                asm volatile("bar.sync 1, 160;");
                for (int c = 0; c < NCHUNK; c++, cc++) {
                    const int s = cc % NSTAGE;
                    const int par = (cc / NSTAGE) & 1;
                    MBARRIER_WAIT_PARITY(sbase + SM_FULL0 + 8 * s, par);
                    FENCE_PROXY_ASYNC();
                    if (elect1()) {
#pragma unroll
                        for (int kk = 0; kk < 2; kk++) {
                            const uint32_t en0 = (c == 0 && kk == 0) ? 0u : 1u;
                            mma_f16_ss(tmem + 0,   dAhi[s] + kk * 2,       dBhi[s] + kk * 2, en0);
                            mma_f16_ss(tmem + 256, dAhi[s] + 512 + kk * 2, dBhi[s] + kk * 2, en0);
                            mma_f16_ss(tmem + 0,   dAlo[s] + kk * 2,       dBhi[s] + kk * 2, 1u);
                            mma_f16_ss(tmem + 256, dAlo[s] + 512 + kk * 2, dBhi[s] + kk * 2, 1u);
                            mma_f16_ss(tmem + 0,   dAhi[s] + kk * 2,       dBlo[s] + kk * 2, 1u);
                            mma_f16_ss(tmem + 256, dAhi[s] + 512 + kk * 2, dBlo[s] + kk * 2, 1u);
                        }
                        TCGEN05_COMMIT(sbase + SM_EMPTY0 + 8 * s);
                    }
                }
                if (elect1()) TCGEN05_COMMIT(sbase + SM_DONE);
            }
            GRID_SYNC(t);
        }
    } else if (wid <= 4) {
        // ================= producer warps =================
        const int pid = tid - 32;             // 0..127
        const int r0 = pid >> 2;              // 0..31
        const int c16 = pid & 3;              // 16B col within 64B row
        uint32_t so[8];
#pragma unroll
        for (int u = 0; u < 8; u++) so[u] = swz64((r0 + 32 * u) * 64 + c16 * 16);
        int pc = 0;
        for (int t = 0; t < TLEN; t++) {
            const char* gA  = (const char*)Abuf + (size_t)(t & 1) * (NAELEM * 2)
                              + (size_t)(m0 + r0) * (K2 * 2) + c16 * 16;
            const char* gAl = gA + 2048;
            for (int tile = 0; tile < 2; tile++) {
                const int n0 = (ny + tile * 8) * NT;
                const char* gB  = (const char*)Bp + (size_t)(n0 + r0) * (K2 * 2) + c16 * 16;
                const char* gBl = gB + 2048;
                for (int c = 0; c < NCHUNK; c++, pc++) {
                    const int s = pc % NSTAGE;
                    const int par = ((pc / NSTAGE) & 1) ^ 1;
                    MBARRIER_WAIT_PARITY(sbase + SM_EMPTY0 + 8 * s, par);
                    const uint32_t sT = sbase + SM_STAGE + s * STAGE_BYTES;
                    const size_t koff = (size_t)c * 64;
#pragma unroll
                    for (int u = 0; u < 8; u++) {
                        const size_t grow = (size_t)u * 32 * (K2 * 2);
                        cp16(sT + OFF_AHI + so[u], gA  + grow + koff);
                        cp16(sT + OFF_ALO + so[u], gAl + grow + koff);
                        cp16(sT + OFF_BHI + so[u], gB  + grow + koff);
                        cp16(sT + OFF_BLO + so[u], gBl + grow + koff);
                    }
                    cp_arrive(sbase + SM_FULL0 + 8 * s);
                }
            }
            GRID_SYNC(t);
        }
    } else {
        // ================= epilogue warps (5-8; subpartitions 1,2,3,0) =================
        const int rloc = (wid & 3) * 32 + lid;   // local row within 128-row half
        int dc = 0;
        for (int t = 0; t < TLEN; t++) {
            __nv_bfloat16* Aout = Abuf + (size_t)((t + 1) & 1) * NAELEM;
            float xbv[2] = {0.0f, 0.0f};
            for (int tile = 0; tile < 2; tile++) {
                const int nt = ny + tile * 8;
                const int n0 = nt * NT, j0 = n0 >> 2;
                MBARRIER_WAIT_PARITY(sbase + SM_DONE, dc & 1);
                dc++;
                TCGEN05_FENCE_AFTER();
                if (tile == 0 && t > 0) {
                    // fused pred-reduce of previous step (= decoder feedback x_t)
                    const float bo = bout[0];
#pragma unroll
                    for (int half = 0; half < 2; half++) {
                        const int m = m0 + half * 128 + rloc;
                        const float4* pp = (const float4*)(part + (size_t)((t + 1) & 1) * NP + (size_t)m * JT);
                        const float4 p0 = pp[0], p1 = pp[1], p2 = pp[2], p3 = pp[3];
                        float s = bo;
                        s += p0.x + p0.y + p0.z + p0.w;
                        s += p1.x + p1.y + p1.z + p1.w;
                        s += p2.x + p2.y + p2.z + p2.w;
                        s += p3.x + p3.y + p3.z + p3.w;
                        xbv[half] = s;
                        if (ny == 0) out[(size_t)m * TLEN + (t - 1)] = s;
                    }
                }
#pragma unroll 1
                for (int half = 0; half < 2; half++) {
                    const int m = m0 + half * 128 + rloc;
                    const float xb = xbv[half];
                    const size_t mrow = (size_t)m * HDIM;
                    const size_t arow = (size_t)m * K2;
                    float psum = 0.0f;
#pragma unroll 1
                    for (int nc = 0; nc < 8; nc++) {
                        uint32_t r[32];
                        TCGEN05_LD_X32(r, tmem + half * 256 + nc * 32);
                        TCGEN05_WAIT_LD();
                        if (half == 1 && nc == 7)
                            asm volatile("bar.arrive 1, 160;");  // release MMA for next tile
                        const int nb = n0 + nc * 32;
                        const int jb = j0 + nc * 8;
                        const float4 ca = *(const float4*)(cbuf + mrow + jb);
                        const float4 cb2 = *(const float4*)(cbuf + mrow + jb + 4);
                        float cold[8] = {ca.x, ca.y, ca.z, ca.w, cb2.x, cb2.y, cb2.z, cb2.w};
                        float cn[8];
                        union { __nv_bfloat16 b[8]; uint4 v; } Uhi, Ulo;
#pragma unroll
                        for (int jl = 0; jl < 8; jl++) {
                            const int nn = nb + jl * 4;
                            float iv = __uint_as_float(r[jl * 4 + 0]) + biasp[nn + 0] + xb * wihp[nn + 0];
                            float fv = __uint_as_float(r[jl * 4 + 1]) + biasp[nn + 1] + xb * wihp[nn + 1];
                            float gv = __uint_as_float(r[jl * 4 + 2]) + biasp[nn + 2] + xb * wihp[nn + 2];
                            float ov = __uint_as_float(r[jl * 4 + 3]) + biasp[nn + 3] + xb * wihp[nn + 3];
                            const float si = __fdividef(1.0f, 1.0f + __expf(-iv));
                            const float sf = __fdividef(1.0f, 1.0f + __expf(-fv));
                            const float so2 = __fdividef(1.0f, 1.0f + __expf(-ov));
                            const float tg = 1.0f - __fdividef(2.0f, __expf(2.0f * gv) + 1.0f);
                            const float c2 = sf * cold[jl] + si * tg;
                            const float tc = 1.0f - __fdividef(2.0f, __expf(2.0f * c2) + 1.0f);
                            const float hn = so2 * tc;
                            cn[jl] = c2;
                            const __nv_bfloat16 hi = __float2bfloat16_rn(hn);
                            Uhi.b[jl] = hi;
                            Ulo.b[jl] = __float2bfloat16_rn(hn - __bfloat162float(hi));
                            psum = fmaf(hn, woutp[jb + jl], psum);
                        }
                        *(float4*)(cbuf + mrow + jb)     = make_float4(cn[0], cn[1], cn[2], cn[3]);
                        *(float4*)(cbuf + mrow + jb + 4) = make_float4(cn[4], cn[5], cn[6], cn[7]);
                        *(uint4*)(Aout + arow + jb)        = Uhi.v;   // h_hi
                        *(uint4*)(Aout + arow + 1024 + jb) = Ulo.v;   // h_lo
                    }
                    part[(size_t)(t & 1) * NP + (size_t)m * JT + nt] = psum;
                }
            }
            GRID_SYNC(t);
        }
    }

    // final output column (t = TLEN-1), partials visible after last grid sync
    if (wid >= 5 && ny == 0) {
        const int rloc = (wid & 3) * 32 + lid;
        const float bo = bout[0];
#pragma unroll
        for (int half = 0; half < 2; half++) {
            const int m = m0 + half * 128 + rloc;
            const float4* pp = (const float4*)(part + (size_t)((TLEN - 1) & 1) * NP + (size_t)m * JT);
            const float4 p0 = pp[0], p1 = pp[1], p2 = pp[2], p3 = pp[3];
            float s = bo;
            s += p0.x + p0.y + p0.z + p0.w;
            s += p1.x + p1.y + p1.z + p1.w;
            s += p2.x + p2.y + p2.z + p2.w;
            s += p3.x + p3.y + p3.z + p3.w;
            out[(size_t)m * TLEN + (TLEN - 1)] = s;
        }
    }
    __syncthreads();
    if (wid == 0) TCGEN05_DEALLOC(tmem, 512);
#endif
}

// ---------------- launch ----------------
extern "C" void kernel_launch(void* const* d_in, const int* in_sizes, int n_in,
                              void* d_out, int out_size)
{
    const float* hidden = (const float*)d_in[0];
    const float* cell   = (const float*)d_in[1];
    const float* W_ih   = (const float*)d_in[2];
    const float* W_hh   = (const float*)d_in[3];
    const float* b_ih   = (const float*)d_in[4];
    const float* b_hh   = (const float*)d_in[5];
    const float* W_out  = (const float*)d_in[6];
    const float* b_out  = (const float*)d_in[7];
    float* out = (float*)d_out;

    __nv_bfloat16 *Abuf, *Bp;
    float *cbuf, *biasp, *wihp, *woutp, *part;
    cudaGetSymbolAddress((void**)&Abuf,  g_A);
    cudaGetSymbolAddress((void**)&Bp,    g_Bp);
    cudaGetSymbolAddress((void**)&cbuf,  g_c);
    cudaGetSymbolAddress((void**)&biasp, g_biasp);
    cudaGetSymbolAddress((void**)&wihp,  g_wihp);
    cudaGetSymbolAddress((void**)&woutp, g_woutp);
    cudaGetSymbolAddress((void**)&part,  g_partial);

    cudaFuncSetAttribute(lstm_persist, cudaFuncAttributeMaxDynamicSharedMemorySize, DSMEM);

    prep_weights<<<(NGATE * HDIM + 255) / 256, 256>>>(W_ih, W_hh, b_ih, b_hh, W_out,
                                                      Bp, biasp, wihp, woutp);
    prep_state<<<(BSZ * HDIM + 255) / 256, 256>>>(hidden, cell, Abuf, cbuf);

    lstm_persist<<<NCTA, NTHREADS, DSMEM>>>(Abuf, Bp, cbuf, biasp, wihp, woutp,
                                            part, b_out, out);
}

// round 6
// speedup vs baseline: 1.4318x; 1.4318x over previous
#include <cuda_runtime.h>
#include <cuda_fp16.h>
#include <math.h>
#include <stdint.h>

// ---------------- problem constants ----------------
#define HDIM  1024
#define BSZ   4096
#define TLEN  128
#define K2    2048            // stored K layout: [h_hi | h_lo] (fp16)
#define NGATE 4096            // 4 gates x HDIM, interleaved n' = j*4 + g
#define MT    256
#define NT    256
#define NCHUNK 32             // K chunks of 32 elems (64B rows, SW64)
#define NSTAGE 3
#define JT    16

#if defined(__CUDA_ARCH__) && (defined(__CUDA_ARCH_FEAT_SM103_ALL) || defined(__CUDA_ARCH_FEAT_SM100_ALL) || defined(__CUDA_ARCH_FEAT_SM101_ALL))
#define HAS_TCGEN05 1
#else
#define HAS_TCGEN05 0
#endif

// ---------------- persistent device state ----------------
__device__ __half g_A[2][(size_t)BSZ * K2];       // activations [h_hi|h_lo] fp16 (ping-pong)
__device__ __half g_Bp[(size_t)NGATE * HDIM];     // weights fp16, gate-interleaved rows
__device__ float g_c[(size_t)BSZ * HDIM];
__device__ float g_biasp[NGATE];
__device__ float g_wihp[NGATE];
__device__ float g_woutp[HDIM];
__device__ float g_partial[2][(size_t)BSZ * JT];  // double-buffered

// ---------------- smem layout ----------------
#define SM_TMEM   0
#define SM_FULL0  64
#define SM_EMPTY0 (SM_FULL0 + 8*NSTAGE)
#define SM_DONE   (SM_EMPTY0 + 8*NSTAGE)
#define SM_STAGE  1024
#define STAGE_BYTES 49152       // A_hi 16K | A_lo 16K | B 16K
#define OFF_AHI 0
#define OFF_ALO 16384
#define OFF_B   32768
#define DSMEM (SM_STAGE + NSTAGE*STAGE_BYTES)
#define N_PROD_THREADS 128

// idesc: F32 accum, F16 a/b, N=256, M=128
#define MMA_IDESC 0x08400010u

// ---------------- arch-neutral helpers ----------------
__device__ __forceinline__ uint32_t smem_u32(const void* p) {
    uint32_t a;
    asm("{ .reg .u64 t; cvta.to.shared.u64 t, %1; cvt.u32.u64 %0, t; }" : "=r"(a) : "l"(p));
    return a;
}
__device__ __forceinline__ uint32_t elect1() {
    uint32_t r;
    asm volatile("{ .reg .pred p; elect.sync _|p, 0xFFFFFFFF; selp.b32 %0, 1, 0, p; }" : "=r"(r));
    return r;
}
#define MBARRIER_INIT(addr, cnt) \
    asm volatile("mbarrier.init.shared.b64 [%0], %1;" :: "r"((uint32_t)(addr)), "r"((uint32_t)(cnt)) : "memory")
#define MBARRIER_WAIT_PARITY(addr, par) do { \
    uint32_t _m = (uint32_t)(addr); uint32_t _p = (uint32_t)(par); uint32_t _d; \
    asm volatile("{ .reg .pred p; mbarrier.try_wait.parity.acquire.cta.shared::cta.b64 p, [%1], %2; selp.b32 %0,1,0,p; }" \
        : "=r"(_d) : "r"(_m), "r"(_p) : "memory"); \
    if (!_d) { \
        asm volatile("{ .reg .pred P1; WL_%=: mbarrier.try_wait.parity.acquire.cta.shared::cta.b64 P1, [%0], %1, 0x989680; @P1 bra.uni WD_%=; bra.uni WL_%=; WD_%=: }" \
            :: "r"(_m), "r"(_p) : "memory"); \
    } } while (0)
__device__ __forceinline__ void cp16(uint32_t saddr, const void* gaddr) {
    asm volatile("cp.async.cg.shared.global [%0], [%1], 16;" :: "r"(saddr), "l"(gaddr));
}
__device__ __forceinline__ void cp_arrive(uint32_t mbar) {
    asm volatile("cp.async.mbarrier.arrive.noinc.shared::cta.b64 [%0];" :: "r"(mbar) : "memory");
}
__device__ __forceinline__ uint32_t swz64(uint32_t o) { return o ^ ((o >> 3) & 0x30); }

// SW64 K-major smem descriptor: layout 4, version 1, SBO=32, LBO=1
static __device__ __forceinline__ uint64_t make_desc_sw64(uint32_t addr) {
    const uint64_t base = (uint64_t(4) << 61) | (uint64_t(1) << 46) | (uint64_t(32) << 32) | (uint64_t(1) << 16);
    return base | ((uint64_t)(addr >> 4) & 0x3FFF);
}

// ---------------- tcgen05 (sm_103a-only PTX pass) ----------------
#if HAS_TCGEN05
#define TCGEN05_ALLOC(sa, n) \
    asm volatile("tcgen05.alloc.cta_group::1.sync.aligned.shared::cta.b32 [%0], %1;" :: "r"((uint32_t)(sa)), "r"((uint32_t)(n)) : "memory")
#define TCGEN05_DEALLOC(t, n) \
    asm volatile("tcgen05.dealloc.cta_group::1.sync.aligned.b32 %0, %1;" :: "r"(t), "r"((uint32_t)(n)))
#define TCGEN05_RELINQUISH() \
    asm volatile("tcgen05.relinquish_alloc_permit.cta_group::1.sync.aligned;")
#define TCGEN05_COMMIT(mb) \
    asm volatile("tcgen05.commit.cta_group::1.mbarrier::arrive::one.shared::cluster.b64 [%0];" :: "r"((uint32_t)(mb)) : "memory")
#define TCGEN05_FENCE_AFTER()  asm volatile("tcgen05.fence::after_thread_sync;" ::: "memory")
#define TCGEN05_WAIT_LD()      asm volatile("tcgen05.wait::ld.sync.aligned;" ::: "memory")
#define FENCE_PROXY_ASYNC()    asm volatile("fence.proxy.async.shared::cta;" ::: "memory")

#define TCGEN05_LD_X32(r, ta) \
    asm volatile("tcgen05.ld.sync.aligned.32x32b.x32.b32 " \
        "{%0,%1,%2,%3,%4,%5,%6,%7,%8,%9,%10,%11,%12,%13,%14,%15," \
        "%16,%17,%18,%19,%20,%21,%22,%23,%24,%25,%26,%27,%28,%29,%30,%31}, [%32];" \
        : "=r"((r)[0]),"=r"((r)[1]),"=r"((r)[2]),"=r"((r)[3]),"=r"((r)[4]),"=r"((r)[5]),"=r"((r)[6]),"=r"((r)[7]), \
          "=r"((r)[8]),"=r"((r)[9]),"=r"((r)[10]),"=r"((r)[11]),"=r"((r)[12]),"=r"((r)[13]),"=r"((r)[14]),"=r"((r)[15]), \
          "=r"((r)[16]),"=r"((r)[17]),"=r"((r)[18]),"=r"((r)[19]),"=r"((r)[20]),"=r"((r)[21]),"=r"((r)[22]),"=r"((r)[23]), \
          "=r"((r)[24]),"=r"((r)[25]),"=r"((r)[26]),"=r"((r)[27]),"=r"((r)[28]),"=r"((r)[29]),"=r"((r)[30]),"=r"((r)[31]) \
        : "r"(ta))

__device__ __forceinline__ void mma_f16_ss(uint32_t d, uint64_t ad, uint64_t bd, uint32_t en) {
    asm volatile(
        "{ .reg .pred p; setp.ne.u32 p, %4, 0;\n\t"
        "tcgen05.mma.cta_group::1.kind::f16 [%0], %1, %2, %3, {%5,%5,%5,%5}, p; }"
        :: "r"(d), "l"(ad), "l"(bd), "r"(MMA_IDESC), "r"(en), "r"(0u) : "memory");
}
#endif

// ---------------- prep kernels ----------------
__global__ void prep_weights(const float* __restrict__ W_ih, const float* __restrict__ W_hh,
                             const float* __restrict__ b_ih, const float* __restrict__ b_hh,
                             const float* __restrict__ W_out,
                             __half* __restrict__ Bp, float* __restrict__ biasp,
                             float* __restrict__ wihp, float* __restrict__ woutp)
{
    int idx = blockIdx.x * blockDim.x + threadIdx.x;
    if (idx >= NGATE * HDIM) return;
    int np = idx / HDIM, k = idx - np * HDIM;
    int gg = np & 3, j = np >> 2;
    int src = gg * HDIM + j;
    Bp[(size_t)np * HDIM + k] = __float2half_rn(W_hh[(size_t)src * HDIM + k]);
    if (k == 0) { biasp[np] = b_ih[src] + b_hh[src]; wihp[np] = W_ih[src]; }
    if (np == 0) woutp[k] = W_out[k];
}

__global__ void prep_state(const float* __restrict__ hidden, const float* __restrict__ cell,
                           __half* __restrict__ A0, float* __restrict__ cbuf)
{
    int idx = blockIdx.x * blockDim.x + threadIdx.x;
    if (idx >= BSZ * HDIM) return;
    int m = idx / HDIM, k = idx - m * HDIM;
    float h = hidden[idx];
    __half hi = __float2half_rn(h);
    __half lo = __float2half_rn(h - __half2float(hi));
    A0[(size_t)m * K2 + k]        = hi;
    A0[(size_t)m * K2 + 1024 + k] = lo;
    cbuf[idx] = cell[idx];
}

// ---------------- fused LSTM step ----------------
// gates = W·h_hi + W·h_lo  (fp16 inputs, fp32 TMEM accum; exact in h, W quantized fp16)
__global__ void __launch_bounds__(256, 1)
lstm_step_mma(const __half* __restrict__ Ain, __half* __restrict__ Aout,
              const __half* __restrict__ Bp, float* __restrict__ cbuf,
              const float* __restrict__ biasp, const float* __restrict__ wihp,
              const float* __restrict__ woutp,
              const float* __restrict__ partial_prev, float* __restrict__ partial,
              const float* __restrict__ b_out, float* __restrict__ out,
              int t, int use_x)
{
#if HAS_TCGEN05
    extern __shared__ char smem[];
    const uint32_t sbase = smem_u32(smem);
    const int tid = threadIdx.x, wid = tid >> 5, lid = tid & 31;
    const int m0 = blockIdx.x * MT, n0 = blockIdx.y * NT, j0 = n0 >> 2;

    if (tid == 0) {
#pragma unroll
        for (int s = 0; s < NSTAGE; s++) {
            MBARRIER_INIT(sbase + SM_FULL0 + 8 * s, N_PROD_THREADS);
            MBARRIER_INIT(sbase + SM_EMPTY0 + 8 * s, 1);
        }
        MBARRIER_INIT(sbase + SM_DONE, 1);
    }
    if (wid == 0) TCGEN05_ALLOC(sbase + SM_TMEM, 512);
    __syncthreads();
    uint32_t tmem;
    asm volatile("ld.shared.b32 %0, [%1];" : "=r"(tmem) : "r"(sbase + SM_TMEM));

    if (wid == 0) {
        // -------- MMA warp: 2 terms (A_hi·B, A_lo·B) per chunk --------
        TCGEN05_RELINQUISH();
        for (int c = 0; c < NCHUNK; c++) {
            const int s = c % NSTAGE;
            const int par = (c / NSTAGE) & 1;
            MBARRIER_WAIT_PARITY(sbase + SM_FULL0 + 8 * s, par);
            FENCE_PROXY_ASYNC();
            if (elect1()) {
                const uint32_t aT = sbase + SM_STAGE + s * STAGE_BYTES;
                const uint64_t dAhi = make_desc_sw64(aT + OFF_AHI);
                const uint64_t dAlo = make_desc_sw64(aT + OFF_ALO);
                const uint64_t dB   = make_desc_sw64(aT + OFF_B);
                // m-half offset: 128 rows * 64B = 8192B = 512 desc units
#pragma unroll
                for (int kk = 0; kk < 2; kk++) {
                    const uint32_t en0 = (c == 0 && kk == 0) ? 0u : 1u;
                    mma_f16_ss(tmem + 0,   dAhi + kk * 2,       dB + kk * 2, en0);
                    mma_f16_ss(tmem + 256, dAhi + 512 + kk * 2, dB + kk * 2, en0);
                    mma_f16_ss(tmem + 0,   dAlo + kk * 2,       dB + kk * 2, 1u);
                    mma_f16_ss(tmem + 256, dAlo + 512 + kk * 2, dB + kk * 2, 1u);
                }
                TCGEN05_COMMIT(sbase + SM_EMPTY0 + 8 * s);
            }
        }
        if (elect1()) TCGEN05_COMMIT(sbase + SM_DONE);
    } else if (wid <= 4) {
        // -------- producers: 3 tiles x 16KB per chunk --------
        const int pid = tid - 32;             // 0..127
        const int r0 = pid >> 2;              // 0..31
        const int c16 = pid & 3;              // 16B col within 64B row
        const char* gAh = (const char*)Ain + (size_t)(m0 + r0) * (K2 * 2) + c16 * 16;
        const char* gAl = gAh + 2048;         // +1024 fp16 elems
        const char* gB  = (const char*)Bp + (size_t)(n0 + r0) * (HDIM * 2) + c16 * 16;
        uint32_t so[8];
#pragma unroll
        for (int u = 0; u < 8; u++) so[u] = swz64((r0 + 32 * u) * 64 + c16 * 16);

        for (int c = 0; c < NCHUNK; c++) {
            const int s = c % NSTAGE;
            const int par = ((c / NSTAGE) & 1) ^ 1;
            MBARRIER_WAIT_PARITY(sbase + SM_EMPTY0 + 8 * s, par);
            const uint32_t sT = sbase + SM_STAGE + s * STAGE_BYTES;
            const size_t koff = (size_t)c * 64;      // 32 elems = 64B along K
#pragma unroll
            for (int u = 0; u < 8; u++) {
                const size_t growA = (size_t)u * 32 * (K2 * 2);
                const size_t growB = (size_t)u * 32 * (HDIM * 2);
                cp16(sT + OFF_AHI + so[u], gAh + growA + koff);
                cp16(sT + OFF_ALO + so[u], gAl + growA + koff);
                cp16(sT + OFF_B   + so[u], gB  + growB + koff);
            }
            cp_arrive(sbase + SM_FULL0 + 8 * s);
        }
    }

    // -------- fused epilogue (all 8 warps) --------
    MBARRIER_WAIT_PARITY(sbase + SM_DONE, 0);
    TCGEN05_FENCE_AFTER();

    const int half = wid >> 2;
    const int m = m0 + half * 128 + (wid & 3) * 32 + lid;

    // fused pred-reduce of PREVIOUS step (decoder feedback)
    float xb = 0.0f;
    if (use_x) {
        const float4* pp = (const float4*)(partial_prev + (size_t)m * JT);
        float4 p0 = pp[0], p1 = pp[1], p2 = pp[2], p3 = pp[3];
        float s = b_out[0];
        s += p0.x + p0.y + p0.z + p0.w;
        s += p1.x + p1.y + p1.z + p1.w;
        s += p2.x + p2.y + p2.z + p2.w;
        s += p3.x + p3.y + p3.z + p3.w;
        xb = s;
        if (blockIdx.y == 0) out[(size_t)m * TLEN + (t - 1)] = s;
    }

    const uint32_t dbase = tmem + half * 256;
    const size_t mrow = (size_t)m * HDIM;
    const size_t arow = (size_t)m * K2;
    float psum = 0.0f;

#pragma unroll 1
    for (int nc2 = 0; nc2 < 4; nc2++) {
        uint32_t ra[32], rb[32];
        TCGEN05_LD_X32(ra, dbase + nc2 * 64);
        TCGEN05_LD_X32(rb, dbase + nc2 * 64 + 32);
        TCGEN05_WAIT_LD();
#pragma unroll
        for (int h2 = 0; h2 < 2; h2++) {
            const uint32_t* r = h2 ? rb : ra;
            const int nc = nc2 * 2 + h2;
            const int nb = n0 + nc * 32;
            const int jb = j0 + nc * 8;
            const float4 ca = *(const float4*)(cbuf + mrow + jb);
            const float4 cb2 = *(const float4*)(cbuf + mrow + jb + 4);
            float cold[8] = {ca.x, ca.y, ca.z, ca.w, cb2.x, cb2.y, cb2.z, cb2.w};
            float cn[8];
            union { __half h[8]; uint4 v; } Uhi, Ulo;
#pragma unroll
            for (int jl = 0; jl < 8; jl++) {
                const int nn = nb + jl * 4;
                float iv = __uint_as_float(r[jl * 4 + 0]) + biasp[nn + 0] + xb * wihp[nn + 0];
                float fv = __uint_as_float(r[jl * 4 + 1]) + biasp[nn + 1] + xb * wihp[nn + 1];
                float gv = __uint_as_float(r[jl * 4 + 2]) + biasp[nn + 2] + xb * wihp[nn + 2];
                float ov = __uint_as_float(r[jl * 4 + 3]) + biasp[nn + 3] + xb * wihp[nn + 3];
                const float si = __fdividef(1.0f, 1.0f + __expf(-iv));
                const float sf = __fdividef(1.0f, 1.0f + __expf(-fv));
                const float so2 = __fdividef(1.0f, 1.0f + __expf(-ov));
                const float tg = 1.0f - __fdividef(2.0f, __expf(2.0f * gv) + 1.0f);
                const float c2 = sf * cold[jl] + si * tg;
                const float tc = 1.0f - __fdividef(2.0f, __expf(2.0f * c2) + 1.0f);
                const float hn = so2 * tc;
                cn[jl] = c2;
                const __half hi = __float2half_rn(hn);
                Uhi.h[jl] = hi;
                Ulo.h[jl] = __float2half_rn(hn - __half2float(hi));
                psum = fmaf(hn, woutp[jb + jl], psum);
            }
            *(float4*)(cbuf + mrow + jb)     = make_float4(cn[0], cn[1], cn[2], cn[3]);
            *(float4*)(cbuf + mrow + jb + 4) = make_float4(cn[4], cn[5], cn[6], cn[7]);
            *(uint4*)(Aout + arow + jb)        = Uhi.v;   // h_hi
            *(uint4*)(Aout + arow + 1024 + jb) = Ulo.v;   // h_lo
        }
    }
    partial[(size_t)m * JT + blockIdx.y] = psum;

    __syncthreads();
    if (wid == 0) TCGEN05_DEALLOC(tmem, 512);
#endif
}

// final column (t = TLEN-1) reduce
__global__ void pred_final(const float* __restrict__ partial, const float* __restrict__ b_out,
                           float* __restrict__ out)
{
    const int b = blockIdx.x * blockDim.x + threadIdx.x;
    if (b < BSZ) {
        float s = b_out[0];
        const float* p = partial + (size_t)b * JT;
#pragma unroll
        for (int i = 0; i < JT; i++) s += p[i];
        out[(size_t)b * TLEN + (TLEN - 1)] = s;
    }
}

// ---------------- launch ----------------
extern "C" void kernel_launch(void* const* d_in, const int* in_sizes, int n_in,
                              void* d_out, int out_size)
{
    const float* hidden = (const float*)d_in[0];
    const float* cell   = (const float*)d_in[1];
    const float* W_ih   = (const float*)d_in[2];
    const float* W_hh   = (const float*)d_in[3];
    const float* b_ih   = (const float*)d_in[4];
    const float* b_hh   = (const float*)d_in[5];
    const float* W_out  = (const float*)d_in[6];
    const float* b_out  = (const float*)d_in[7];
    float* out = (float*)d_out;

    __half *Abuf, *Bp;
    float *cbuf, *biasp, *wihp, *woutp, *part;
    cudaGetSymbolAddress((void**)&Abuf,  g_A);
    cudaGetSymbolAddress((void**)&Bp,    g_Bp);
    cudaGetSymbolAddress((void**)&cbuf,  g_c);
    cudaGetSymbolAddress((void**)&biasp, g_biasp);
    cudaGetSymbolAddress((void**)&wihp,  g_wihp);
    cudaGetSymbolAddress((void**)&woutp, g_woutp);
    cudaGetSymbolAddress((void**)&part,  g_partial);

    cudaFuncSetAttribute(lstm_step_mma, cudaFuncAttributeMaxDynamicSharedMemorySize, DSMEM);

    prep_weights<<<(NGATE * HDIM + 255) / 256, 256>>>(W_ih, W_hh, b_ih, b_hh, W_out,
                                                      Bp, biasp, wihp, woutp);
    prep_state<<<(BSZ * HDIM + 255) / 256, 256>>>(hidden, cell, Abuf, cbuf);

    const size_t NA = (size_t)BSZ * K2;
    const size_t NP = (size_t)BSZ * JT;
    dim3 grid(BSZ / MT, NGATE / NT);
    for (int t = 0; t < TLEN; t++) {
        const __half* Ain = Abuf + (size_t)(t & 1) * NA;
        __half* Aout = Abuf + (size_t)((t + 1) & 1) * NA;
        const float* ppart = part + (size_t)((t + 1) & 1) * NP;  // (t-1)&1 == (t+1)&1
        float* cpart = part + (size_t)(t & 1) * NP;
        lstm_step_mma<<<grid, 256, DSMEM>>>(Ain, Aout, Bp, cbuf, biasp, wihp, woutp,
                                            ppart, cpart, b_out, out, t, (t > 0) ? 1 : 0);
    }
    pred_final<<<BSZ / 256, 256>>>(part + (size_t)((TLEN - 1) & 1) * NP, b_out, out);
}